// round 10
// baseline (speedup 1.0000x reference)
#include <cuda_runtime.h>
#include <cstdint>

// ---------------------------------------------------------------------------
// GCN 2-layer. R10: bucket-CSR with NO scale pass — dinv folded into gather
// (norm = (w*dinv_s) summed, * dinv_d at the end). R5 tf32 MMA GEMM.
// Side chain: setup -> fill (1 atomic/edge) -> degrow. Hidden under GEMM1.
// ---------------------------------------------------------------------------

#define N_MAX 100000
#define E_MAX 1600000
#define F_DIM 128
#define BUCKET 64

__device__ float g_A[(size_t)N_MAX * F_DIM];            // GEMM output (lin)
__device__ float g_B[(size_t)N_MAX * F_DIM];            // aggregated layer-1
__device__ float g_dinv[N_MAX];
__device__ int   g_cnt[N_MAX];
__device__ int   g_bsrc[(size_t)N_MAX * BUCKET];        // bucket: src idx
__device__ float g_bw[(size_t)N_MAX * BUCKET];          // bucket: raw edge w
__device__ int   g_is64;

// --- fused: int64/int32 detection (block 0) + cnt init ---
__global__ void k_setup(const unsigned* __restrict__ w, int N) {
    int i = blockIdx.x * blockDim.x + threadIdx.x;
    if (i < N) g_cnt[i] = 0;
    if (blockIdx.x == 0) {
        __shared__ unsigned s;
        if (threadIdx.x == 0) s = 0u;
        __syncthreads();
        unsigned v = 0;
        for (int j = threadIdx.x; j < 4096; j += blockDim.x) v |= w[2 * j + 1];
        if (v) atomicOr(&s, 1u);
        __syncthreads();
        if (threadIdx.x == 0) g_is64 = (s == 0u) ? 1 : 0;
    }
}

__device__ __forceinline__ void edge_decode(const void* ei, int E, int e,
                                            int& s, int& d) {
    if (g_is64) {
        const long long* p = (const long long*)ei;
        s = (int)p[e];
        d = (int)p[(size_t)E + e];
    } else {
        const int* p = (const int*)ei;
        s = p[e];
        d = p[(size_t)E + e];
    }
}

// --- single-pass bucket fill: 1 atomic per edge ---
__global__ void k_fill(const void* __restrict__ ei, const float* __restrict__ w, int E) {
    int e = blockIdx.x * blockDim.x + threadIdx.x;
    if (e >= E) return;
    int s, d;
    edge_decode(ei, E, e, s, d);
    int pos = atomicAdd(&g_cnt[d], 1);
    if (pos < BUCKET) {
        size_t slot = (size_t)d * BUCKET + pos;
        g_bsrc[slot] = s;
        g_bw[slot] = w[e];
    }
}

// --- per-node weighted degree (warp reduce over raw w) -> dinv ---
__global__ void k_degrow(int N) {
    int warp = (blockIdx.x * blockDim.x + threadIdx.x) >> 5;
    if (warp >= N) return;
    int lane = threadIdx.x & 31;
    int c = min(g_cnt[warp], BUCKET);
    size_t base = (size_t)warp * BUCKET;
    float s = 0.0f;
    if (lane < c)      s += g_bw[base + lane];
    if (lane + 32 < c) s += g_bw[base + 32 + lane];
#pragma unroll
    for (int o = 16; o > 0; o >>= 1) s += __shfl_xor_sync(0xffffffffu, s, o);
    if (lane == 0) {
        float deg = 1.0f + s;    // self-loop weight 1
        g_dinv[warp] = (deg > 0.0f) ? rsqrtf(deg) : 0.0f;
    }
}

// ---------------------------------------------------------------------------
// tf32 tensor-core GEMM (R5-proven): C[M,128] = act(X[M,K]) @ W[K,128]
// ---------------------------------------------------------------------------
#define SMSTRIDE 40

__device__ __forceinline__ unsigned f2tf(float f) {
    unsigned r;
    asm("cvt.rna.tf32.f32 %0, %1;" : "=r"(r) : "f"(f));
    return r;
}
__device__ __forceinline__ void ldsm4(unsigned& r0, unsigned& r1,
                                      unsigned& r2, unsigned& r3, unsigned a) {
    asm volatile("ldmatrix.sync.aligned.m8n8.x4.shared.b16 {%0,%1,%2,%3}, [%4];"
                 : "=r"(r0), "=r"(r1), "=r"(r2), "=r"(r3) : "r"(a));
}
__device__ __forceinline__ void ldsm2(unsigned& r0, unsigned& r1, unsigned a) {
    asm volatile("ldmatrix.sync.aligned.m8n8.x2.shared.b16 {%0,%1}, [%2];"
                 : "=r"(r0), "=r"(r1) : "r"(a));
}
__device__ __forceinline__ void mma_tf32(float* c, const unsigned* a, const unsigned* b) {
    asm volatile(
        "mma.sync.aligned.m16n8k8.row.col.f32.tf32.tf32.f32 "
        "{%0,%1,%2,%3}, {%4,%5,%6,%7}, {%8,%9}, {%0,%1,%2,%3};"
        : "+f"(c[0]), "+f"(c[1]), "+f"(c[2]), "+f"(c[3])
        : "r"(a[0]), "r"(a[1]), "r"(a[2]), "r"(a[3]), "r"(b[0]), "r"(b[1]));
}

template <bool RELU>
__global__ __launch_bounds__(256) void k_tgemm(
    const float* __restrict__ X, const float* __restrict__ W,
    float* __restrict__ C, int M, int K)
{
    __shared__ __align__(128) unsigned As[128 * SMSTRIDE];
    __shared__ __align__(128) unsigned Bs[128 * SMSTRIDE];

    const int tid = threadIdx.x;
    const int lane = tid & 31;
    const int wid = tid >> 5;
    const int warp_m = wid & 1;
    const int warp_n = wid >> 1;
    const int rowBase = blockIdx.x * 128;

    const unsigned sA = (unsigned)__cvta_generic_to_shared(As);
    const unsigned sB = (unsigned)__cvta_generic_to_shared(Bs);

    const int aRowL = ((lane >> 3) & 1) * 8 + (lane & 7);
    const int aColS = (lane >> 4) * 16;
    const unsigned swzA = ((unsigned)(aRowL & 4)) << 2;
    const int bRowL = lane & 7;
    const int bColS = ((lane >> 3) & 1) * 16;
    const unsigned swzB = ((unsigned)(bRowL & 4)) << 2;

    unsigned aBase[4], bBase[4];
#pragma unroll
    for (int mt = 0; mt < 4; mt++)
        aBase[mt] = sA + ((warp_m * 64 + mt * 16 + aRowL) * SMSTRIDE) * 4 + aColS;
#pragma unroll
    for (int nt = 0; nt < 4; nt++)
        bBase[nt] = sB + ((warp_n * 32 + nt * 8 + bRowL) * SMSTRIDE) * 4 + bColS;

    float acc[4][4][4];
#pragma unroll
    for (int i = 0; i < 4; i++)
#pragma unroll
        for (int j = 0; j < 4; j++)
#pragma unroll
            for (int v = 0; v < 4; v++) acc[i][j][v] = 0.0f;

    for (int k0 = 0; k0 < K; k0 += 32) {
#pragma unroll
        for (int it = 0; it < 4; it++) {
            int idx = it * 256 + tid;
            int row = idx >> 3;
            int c4 = idx & 7;
            float4 xv = make_float4(0.f, 0.f, 0.f, 0.f);
            int gr = rowBase + row;
            if (gr < M) xv = *(const float4*)(X + (size_t)gr * K + k0 + c4 * 4);
            if (RELU) {
                xv.x = fmaxf(xv.x, 0.f); xv.y = fmaxf(xv.y, 0.f);
                xv.z = fmaxf(xv.z, 0.f); xv.w = fmaxf(xv.w, 0.f);
            }
            uint4 tv = make_uint4(f2tf(xv.x), f2tf(xv.y), f2tf(xv.z), f2tf(xv.w));
            unsigned boff = row * SMSTRIDE * 4 + ((c4 * 16) ^ (((unsigned)(row & 4)) << 2));
            *(uint4*)((char*)As + boff) = tv;
        }
#pragma unroll
        for (int it = 0; it < 4; it++) {
            int idx = it * 256 + tid;
            int kr = idx >> 5;
            int n4 = idx & 31;
            float4 wv = *(const float4*)(W + (size_t)(k0 + kr) * 128 + n4 * 4);
            unsigned t0 = f2tf(wv.x), t1 = f2tf(wv.y), t2 = f2tf(wv.z), t3 = f2tf(wv.w);
            int r0 = n4 * 4;
#pragma unroll
            for (int j = 0; j < 4; j++) {
                unsigned tj = (j == 0) ? t0 : (j == 1) ? t1 : (j == 2) ? t2 : t3;
                int row = r0 + j;
                unsigned boff = row * SMSTRIDE * 4 + ((kr * 4) ^ (((unsigned)(row & 4)) << 2));
                *(unsigned*)((char*)Bs + boff) = tj;
            }
        }
        __syncthreads();

#pragma unroll
        for (int ks = 0; ks < 4; ks++) {
            unsigned afrag[4][4], bfrag[4][2];
#pragma unroll
            for (int mt = 0; mt < 4; mt++)
                ldsm4(afrag[mt][0], afrag[mt][1], afrag[mt][2], afrag[mt][3],
                      (aBase[mt] + ks * 32) ^ swzA);
#pragma unroll
            for (int nt = 0; nt < 4; nt++)
                ldsm2(bfrag[nt][0], bfrag[nt][1], (bBase[nt] + ks * 32) ^ swzB);
#pragma unroll
            for (int mt = 0; mt < 4; mt++)
#pragma unroll
                for (int nt = 0; nt < 4; nt++)
                    mma_tf32(acc[mt][nt], afrag[mt], bfrag[nt]);
        }
        __syncthreads();
    }

    const int crow = lane >> 2;
    const int ccol = (lane & 3) * 2;
#pragma unroll
    for (int mt = 0; mt < 4; mt++) {
        int r0 = rowBase + warp_m * 64 + mt * 16 + crow;
#pragma unroll
        for (int nt = 0; nt < 4; nt++) {
            int col = warp_n * 32 + nt * 8 + ccol;
            if (r0 < M) {
                float2 v = make_float2(acc[mt][nt][0], acc[mt][nt][1]);
                *(float2*)(C + (size_t)r0 * 128 + col) = v;
            }
            if (r0 + 8 < M) {
                float2 v = make_float2(acc[mt][nt][2], acc[mt][nt][3]);
                *(float2*)(C + (size_t)(r0 + 8) * 128 + col) = v;
            }
        }
    }
}

// ---------------------------------------------------------------------------
// Bucket gather with inline norm: one warp per dst node.
// out[d] = dinv_d * Sum_e (w_e*dinv[src_e]) * lin[src_e] + dinv_d^2*lin[d] + b
// ---------------------------------------------------------------------------
__global__ __launch_bounds__(256) void k_gather(
    const float* __restrict__ lin, const float* __restrict__ bias,
    float* __restrict__ out, int N)
{
    int warp = (blockIdx.x * blockDim.x + threadIdx.x) >> 5;
    if (warp >= N) return;
    int lane = threadIdx.x & 31;
    int d = warp;

    float4 acc = make_float4(0.f, 0.f, 0.f, 0.f);   // edge sum (unnormalized by dinv_d)
    int c = min(g_cnt[d], BUCKET);
    size_t base = (size_t)d * BUCKET;
    int e = 0;
    for (; e + 3 < c; e += 4) {
        int s0 = g_bsrc[base + e];
        int s1 = g_bsrc[base + e + 1];
        int ss2 = g_bsrc[base + e + 2];
        int s3 = g_bsrc[base + e + 3];
        float n0 = g_bw[base + e]     * g_dinv[s0];
        float n1 = g_bw[base + e + 1] * g_dinv[s1];
        float n2 = g_bw[base + e + 2] * g_dinv[ss2];
        float n3 = g_bw[base + e + 3] * g_dinv[s3];
        float4 u0 = ((const float4*)lin)[(size_t)s0 * 32 + lane];
        float4 u1 = ((const float4*)lin)[(size_t)s1 * 32 + lane];
        float4 u2 = ((const float4*)lin)[(size_t)ss2 * 32 + lane];
        float4 u3 = ((const float4*)lin)[(size_t)s3 * 32 + lane];
        acc.x = fmaf(u0.x, n0, acc.x); acc.y = fmaf(u0.y, n0, acc.y);
        acc.z = fmaf(u0.z, n0, acc.z); acc.w = fmaf(u0.w, n0, acc.w);
        acc.x = fmaf(u1.x, n1, acc.x); acc.y = fmaf(u1.y, n1, acc.y);
        acc.z = fmaf(u1.z, n1, acc.z); acc.w = fmaf(u1.w, n1, acc.w);
        acc.x = fmaf(u2.x, n2, acc.x); acc.y = fmaf(u2.y, n2, acc.y);
        acc.z = fmaf(u2.z, n2, acc.z); acc.w = fmaf(u2.w, n2, acc.w);
        acc.x = fmaf(u3.x, n3, acc.x); acc.y = fmaf(u3.y, n3, acc.y);
        acc.z = fmaf(u3.z, n3, acc.z); acc.w = fmaf(u3.w, n3, acc.w);
    }
    for (; e < c; e++) {
        int s0 = g_bsrc[base + e];
        float n0 = g_bw[base + e] * g_dinv[s0];
        float4 u0 = ((const float4*)lin)[(size_t)s0 * 32 + lane];
        acc.x = fmaf(u0.x, n0, acc.x); acc.y = fmaf(u0.y, n0, acc.y);
        acc.z = fmaf(u0.z, n0, acc.z); acc.w = fmaf(u0.w, n0, acc.w);
    }

    float di = g_dinv[d];
    float s2 = di * di;
    float4 b4 = ((const float4*)bias)[lane];
    float4 v = ((const float4*)lin)[(size_t)d * 32 + lane];
    float4 o;
    o.x = fmaf(acc.x, di, fmaf(v.x, s2, b4.x));
    o.y = fmaf(acc.y, di, fmaf(v.y, s2, b4.y));
    o.z = fmaf(acc.z, di, fmaf(v.z, s2, b4.z));
    o.w = fmaf(acc.w, di, fmaf(v.w, s2, b4.w));
    ((float4*)out)[(size_t)d * 32 + lane] = o;
}

// ---------------------------------------------------------------------------

static inline int cdiv(long long a, long long b) { return (int)((a + b - 1) / b); }

extern "C" void kernel_launch(void* const* d_in, const int* in_sizes, int n_in,
                              void* d_out, int out_size)
{
    const float* x   = (const float*)d_in[0];
    const void*  ei  = d_in[1];
    const float* ew  = (const float*)d_in[2];
    const float* W1  = (const float*)d_in[3];
    const float* b1  = (const float*)d_in[4];
    const float* W2  = (const float*)d_in[5];
    const float* b2  = (const float*)d_in[6];
    float* out = (float*)d_out;

    const int HID = in_sizes[4];                 // 128
    const int K1  = in_sizes[3] / HID;           // 256
    const int N   = in_sizes[0] / K1;            // 100000
    const int E   = in_sizes[2];                 // 1600000

    float* A; float* B;
    cudaGetSymbolAddress((void**)&A, g_A);
    cudaGetSymbolAddress((void**)&B, g_B);

    const int T = 256;

    // Fork-join (R7-proven resource pattern: 1 side stream, 2 events).
    cudaStream_t side;
    cudaStreamCreateWithFlags(&side, cudaStreamNonBlocking);
    cudaEvent_t evFork, evJoin;
    cudaEventCreateWithFlags(&evFork, cudaEventDisableTiming);
    cudaEventCreateWithFlags(&evJoin, cudaEventDisableTiming);

    cudaEventRecord(evFork, 0);
    cudaStreamWaitEvent(side, evFork, 0);

    // --- side stream: bucket-CSR build (hidden under GEMM1) ---
    k_setup<<<cdiv(N, T), T, 0, side>>>((const unsigned*)ei, N);
    k_fill<<<cdiv(E, T), T, 0, side>>>(ei, ew, E);
    k_degrow<<<cdiv((long long)N * 32, T), T, 0, side>>>(N);
    cudaEventRecord(evJoin, side);

    // --- main stream: layer-1 GEMM (independent of CSR build) ---
    k_tgemm<false><<<cdiv(N, 128), T>>>(x, W1, A, N, K1);

    cudaStreamWaitEvent(0, evJoin, 0);
    k_gather<<<cdiv((long long)N * 32, T), T>>>(A, b1, B, N);

    k_tgemm<true><<<cdiv(N, 128), T>>>(B, W2, A, N, HID);
    k_gather<<<cdiv((long long)N * 32, T), T>>>(A, b2, out, N);
}

// round 11
// speedup vs baseline: 1.4588x; 1.4588x over previous
#include <cuda_runtime.h>
#include <cstdint>

// ---------------------------------------------------------------------------
// GCN 2-layer. R11: R9 pipeline (bucket-CSR + scale on side stream, fp32
// bucket gather) + software-pipelined tf32 MMA GEMM:
//   - A tile: cp.async (raw fp32, zero-fill OOB) double-buffered,
//     tf32 cvt (+ReLU) applied to A-fragments after ldmatrix
//   - W tile: register prefetch during compute, cvt+STS double-buffered
//   - one __syncthreads per BK iteration
// ---------------------------------------------------------------------------

#define N_MAX 100000
#define E_MAX 1600000
#define F_DIM 128
#define BUCKET 64

__device__ float g_A[(size_t)N_MAX * F_DIM];            // GEMM output (lin)
__device__ float g_B[(size_t)N_MAX * F_DIM];            // aggregated layer-1
__device__ float g_dinv[N_MAX];
__device__ int   g_cnt[N_MAX];
__device__ int   g_bsrc[(size_t)N_MAX * BUCKET];        // bucket: src idx
__device__ float g_bw[(size_t)N_MAX * BUCKET];          // bucket: w -> full norm
__device__ int   g_is64;

// --- fused: int64/int32 detection (block 0) + cnt init ---
__global__ void k_setup(const unsigned* __restrict__ w, int N) {
    int i = blockIdx.x * blockDim.x + threadIdx.x;
    if (i < N) g_cnt[i] = 0;
    if (blockIdx.x == 0) {
        __shared__ unsigned s;
        if (threadIdx.x == 0) s = 0u;
        __syncthreads();
        unsigned v = 0;
        for (int j = threadIdx.x; j < 4096; j += blockDim.x) v |= w[2 * j + 1];
        if (v) atomicOr(&s, 1u);
        __syncthreads();
        if (threadIdx.x == 0) g_is64 = (s == 0u) ? 1 : 0;
    }
}

__device__ __forceinline__ void edge_decode(const void* ei, int E, int e,
                                            int& s, int& d) {
    if (g_is64) {
        const long long* p = (const long long*)ei;
        s = (int)p[e];
        d = (int)p[(size_t)E + e];
    } else {
        const int* p = (const int*)ei;
        s = p[e];
        d = p[(size_t)E + e];
    }
}

// --- single-pass bucket fill: 1 atomic per edge ---
__global__ void k_fill(const void* __restrict__ ei, const float* __restrict__ w, int E) {
    int e = blockIdx.x * blockDim.x + threadIdx.x;
    if (e >= E) return;
    int s, d;
    edge_decode(ei, E, e, s, d);
    int pos = atomicAdd(&g_cnt[d], 1);
    if (pos < BUCKET) {
        size_t slot = (size_t)d * BUCKET + pos;
        g_bsrc[slot] = s;
        g_bw[slot] = w[e];
    }
}

// --- per-node weighted degree (warp reduce) -> dinv ---
__global__ void k_degrow(int N) {
    int warp = (blockIdx.x * blockDim.x + threadIdx.x) >> 5;
    if (warp >= N) return;
    int lane = threadIdx.x & 31;
    int c = min(g_cnt[warp], BUCKET);
    size_t base = (size_t)warp * BUCKET;
    float s = 0.0f;
    if (lane < c)      s += g_bw[base + lane];
    if (lane + 32 < c) s += g_bw[base + 32 + lane];
#pragma unroll
    for (int o = 16; o > 0; o >>= 1) s += __shfl_xor_sync(0xffffffffu, s, o);
    if (lane == 0) {
        float deg = 1.0f + s;    // self-loop weight 1
        g_dinv[warp] = (deg > 0.0f) ? rsqrtf(deg) : 0.0f;
    }
}

// --- fold full norm into bucket weights: wn = dinv[src]*w*dinv[dst] ---
__global__ void k_scale(int N) {
    long long idx = (long long)blockIdx.x * blockDim.x + threadIdx.x;
    if (idx >= (long long)N * BUCKET) return;
    int d = (int)(idx >> 6);
    int j = (int)(idx & 63);
    if (j >= min(g_cnt[d], BUCKET)) return;
    g_bw[idx] = g_bw[idx] * g_dinv[g_bsrc[idx]] * g_dinv[d];
}

// ---------------------------------------------------------------------------
// Software-pipelined tf32 tensor-core GEMM: C[M,128] = act(X[M,K]) @ W[K,128]
// BM=128, BN=128, BK=32; 256 threads (8 warps, 2M x 4N).
// ---------------------------------------------------------------------------
#define SMSTRIDE 40                       // floats per smem row (160 B)
#define ABUF (128 * SMSTRIDE * 4)         // 20480 bytes per buffer
#define DYNSMEM (4 * ABUF)                // 2 A bufs + 2 W bufs

__device__ __forceinline__ unsigned f2tf(float f) {
    unsigned r;
    asm("cvt.rna.tf32.f32 %0, %1;" : "=r"(r) : "f"(f));
    return r;
}
__device__ __forceinline__ void ldsm4(unsigned& r0, unsigned& r1,
                                      unsigned& r2, unsigned& r3, unsigned a) {
    asm volatile("ldmatrix.sync.aligned.m8n8.x4.shared.b16 {%0,%1,%2,%3}, [%4];"
                 : "=r"(r0), "=r"(r1), "=r"(r2), "=r"(r3) : "r"(a));
}
__device__ __forceinline__ void ldsm2(unsigned& r0, unsigned& r1, unsigned a) {
    asm volatile("ldmatrix.sync.aligned.m8n8.x2.shared.b16 {%0,%1}, [%2];"
                 : "=r"(r0), "=r"(r1) : "r"(a));
}
__device__ __forceinline__ void mma_tf32(float* c, const unsigned* a, const unsigned* b) {
    asm volatile(
        "mma.sync.aligned.m16n8k8.row.col.f32.tf32.tf32.f32 "
        "{%0,%1,%2,%3}, {%4,%5,%6,%7}, {%8,%9}, {%0,%1,%2,%3};"
        : "+f"(c[0]), "+f"(c[1]), "+f"(c[2]), "+f"(c[3])
        : "r"(a[0]), "r"(a[1]), "r"(a[2]), "r"(a[3]), "r"(b[0]), "r"(b[1]));
}
__device__ __forceinline__ void cp_async16(unsigned dst, const float* src, int sz) {
    asm volatile("cp.async.ca.shared.global [%0], [%1], 16, %2;"
                 :: "r"(dst), "l"(src), "r"(sz) : "memory");
}
__device__ __forceinline__ void cp_commit() {
    asm volatile("cp.async.commit_group;" ::: "memory");
}
__device__ __forceinline__ void cp_wait0() {
    asm volatile("cp.async.wait_group 0;" ::: "memory");
}

template <bool RELU>
__global__ __launch_bounds__(256) void k_tgemm(
    const float* __restrict__ X, const float* __restrict__ W,
    float* __restrict__ C, int M, int K)
{
    extern __shared__ __align__(128) char dynsm[];
    const unsigned sBase = (unsigned)__cvta_generic_to_shared(dynsm);
    const unsigned sA = sBase;                 // 2 x ABUF raw fp32 X tiles
    const unsigned sB = sBase + 2 * ABUF;      // 2 x ABUF tf32 W tiles [n][k]

    const int tid = threadIdx.x;
    const int lane = tid & 31;
    const int wid = tid >> 5;
    const int warp_m = wid & 1;
    const int warp_n = wid >> 1;
    const int rowBase = blockIdx.x * 128;

    // ldmatrix per-thread addressing (buffer-relative)
    const int aRowL = ((lane >> 3) & 1) * 8 + (lane & 7);
    const int aColS = (lane >> 4) * 16;
    const unsigned swzA = ((unsigned)(aRowL & 4)) << 2;
    const int bRowL = lane & 7;
    const int bColS = ((lane >> 3) & 1) * 16;
    const unsigned swzB = ((unsigned)(bRowL & 4)) << 2;

    unsigned aBase[4], bBase[4];
#pragma unroll
    for (int mt = 0; mt < 4; mt++)
        aBase[mt] = sA + ((warp_m * 64 + mt * 16 + aRowL) * SMSTRIDE) * 4 + aColS;
#pragma unroll
    for (int nt = 0; nt < 4; nt++)
        bBase[nt] = sB + ((warp_n * 32 + nt * 8 + bRowL) * SMSTRIDE) * 4 + bColS;

    float acc[4][4][4];
#pragma unroll
    for (int i = 0; i < 4; i++)
#pragma unroll
        for (int j = 0; j < 4; j++)
#pragma unroll
            for (int v = 0; v < 4; v++) acc[i][j][v] = 0.0f;

    const int NT = K >> 5;                     // BK=32 tiles

    // --- tile issue helpers (inlined manually) ---
    // A: 1024 16B chunks, 4 per thread; raw fp32, zero-fill OOB rows.
#define ISSUE_A(k0, bufsel)                                                    \
    {                                                                          \
        _Pragma("unroll")                                                      \
        for (int it = 0; it < 4; it++) {                                       \
            int idx = it * 256 + tid;                                          \
            int row = idx >> 3;                                                \
            int c4 = idx & 7;                                                  \
            int gr = rowBase + row;                                            \
            int ok = (gr < M);                                                 \
            const float* src = X + (size_t)(ok ? gr : 0) * K + (k0) + c4 * 4;  \
            unsigned dst = sA + (bufsel) * ABUF + row * (SMSTRIDE * 4)         \
                           + (((unsigned)(c4 * 16)) ^ (((unsigned)(row & 4)) << 2)); \
            cp_async16(dst, src, ok ? 16 : 0);                                 \
        }                                                                      \
        cp_commit();                                                           \
    }

#define LOAD_W(k0, wreg)                                                       \
    {                                                                          \
        _Pragma("unroll")                                                      \
        for (int it = 0; it < 4; it++) {                                       \
            int idx = it * 256 + tid;                                          \
            int kr = idx >> 5;                                                 \
            int n4 = idx & 31;                                                 \
            wreg[it] = *(const float4*)(W + (size_t)((k0) + kr) * 128 + n4 * 4); \
        }                                                                      \
    }

#define STORE_W(wreg, bufsel)                                                  \
    {                                                                          \
        char* wb = dynsm + 2 * ABUF + (bufsel) * ABUF;                         \
        _Pragma("unroll")                                                      \
        for (int it = 0; it < 4; it++) {                                       \
            int idx = it * 256 + tid;                                          \
            int kr = idx >> 5;                                                 \
            int n4 = idx & 31;                                                 \
            unsigned t0 = f2tf(wreg[it].x), t1 = f2tf(wreg[it].y);             \
            unsigned t2 = f2tf(wreg[it].z), t3 = f2tf(wreg[it].w);             \
            int r0 = n4 * 4;                                                   \
            _Pragma("unroll")                                                  \
            for (int j = 0; j < 4; j++) {                                      \
                unsigned tj = (j == 0) ? t0 : (j == 1) ? t1 : (j == 2) ? t2 : t3; \
                int row = r0 + j;                                              \
                unsigned boff = row * (SMSTRIDE * 4)                           \
                    + (((unsigned)(kr * 4)) ^ (((unsigned)(row & 4)) << 2));   \
                *(unsigned*)(wb + boff) = tj;                                  \
            }                                                                  \
        }                                                                      \
    }

    // --- prologue: tile 0 ---
    ISSUE_A(0, 0);
    {
        float4 wreg[4];
        LOAD_W(0, wreg);
        STORE_W(wreg, 0);
    }
    cp_wait0();
    __syncthreads();

    for (int i = 0; i < NT; i++) {
        int cur = i & 1;
        int nxt = cur ^ 1;
        bool more = (i + 1 < NT);
        if (more) ISSUE_A((i + 1) * 32, nxt);
        float4 wreg[4];
        if (more) LOAD_W((i + 1) * 32, wreg);

        unsigned abufoff = cur * ABUF;
#pragma unroll
        for (int ks = 0; ks < 4; ks++) {
            unsigned afrag[4][4], bfrag[4][2];
#pragma unroll
            for (int mt = 0; mt < 4; mt++) {
                ldsm4(afrag[mt][0], afrag[mt][1], afrag[mt][2], afrag[mt][3],
                      ((aBase[mt] + abufoff + ks * 32) ^ swzA));
#pragma unroll
                for (int r = 0; r < 4; r++) {
                    float f = __uint_as_float(afrag[mt][r]);
                    if (RELU) f = fmaxf(f, 0.0f);
                    afrag[mt][r] = f2tf(f);
                }
            }
#pragma unroll
            for (int nt = 0; nt < 4; nt++)
                ldsm2(bfrag[nt][0], bfrag[nt][1],
                      ((bBase[nt] + abufoff + ks * 32) ^ swzB));
#pragma unroll
            for (int mt = 0; mt < 4; mt++)
#pragma unroll
                for (int nt = 0; nt < 4; nt++)
                    mma_tf32(acc[mt][nt], afrag[mt], bfrag[nt]);
        }

        if (more) {
            STORE_W(wreg, nxt);
            cp_wait0();
        }
        __syncthreads();
    }

    // --- epilogue ---
    const int crow = lane >> 2;
    const int ccol = (lane & 3) * 2;
#pragma unroll
    for (int mt = 0; mt < 4; mt++) {
        int r0 = rowBase + warp_m * 64 + mt * 16 + crow;
#pragma unroll
        for (int nt = 0; nt < 4; nt++) {
            int col = warp_n * 32 + nt * 8 + ccol;
            if (r0 < M) {
                float2 v = make_float2(acc[mt][nt][0], acc[mt][nt][1]);
                *(float2*)(C + (size_t)r0 * 128 + col) = v;
            }
            if (r0 + 8 < M) {
                float2 v = make_float2(acc[mt][nt][2], acc[mt][nt][3]);
                *(float2*)(C + (size_t)(r0 + 8) * 128 + col) = v;
            }
        }
    }
}

// ---------------------------------------------------------------------------
// Bucket gather (R9-proven): one warp per dst node; norms precomputed.
// out[d] = Sum(wn*lin[s]) + dinv[d]^2*lin[d] + bias
// ---------------------------------------------------------------------------
__global__ __launch_bounds__(256) void k_gather(
    const float* __restrict__ lin, const float* __restrict__ bias,
    float* __restrict__ out, int N)
{
    int warp = (blockIdx.x * blockDim.x + threadIdx.x) >> 5;
    if (warp >= N) return;
    int lane = threadIdx.x & 31;
    int d = warp;

    float di = g_dinv[d];
    float s2 = di * di;
    float4 b4 = ((const float4*)bias)[lane];
    float4 v = ((const float4*)lin)[(size_t)d * 32 + lane];
    float4 acc = make_float4(fmaf(v.x, s2, b4.x), fmaf(v.y, s2, b4.y),
                             fmaf(v.z, s2, b4.z), fmaf(v.w, s2, b4.w));

    int c = min(g_cnt[d], BUCKET);
    size_t base = (size_t)d * BUCKET;
    int e = 0;
    for (; e + 3 < c; e += 4) {
        int s0 = g_bsrc[base + e];      float n0 = g_bw[base + e];
        int s1 = g_bsrc[base + e + 1];  float n1 = g_bw[base + e + 1];
        int ss = g_bsrc[base + e + 2];  float n2 = g_bw[base + e + 2];
        int s3 = g_bsrc[base + e + 3];  float n3 = g_bw[base + e + 3];
        float4 u0 = ((const float4*)lin)[(size_t)s0 * 32 + lane];
        float4 u1 = ((const float4*)lin)[(size_t)s1 * 32 + lane];
        float4 u2 = ((const float4*)lin)[(size_t)ss * 32 + lane];
        float4 u3 = ((const float4*)lin)[(size_t)s3 * 32 + lane];
        acc.x = fmaf(u0.x, n0, acc.x); acc.y = fmaf(u0.y, n0, acc.y);
        acc.z = fmaf(u0.z, n0, acc.z); acc.w = fmaf(u0.w, n0, acc.w);
        acc.x = fmaf(u1.x, n1, acc.x); acc.y = fmaf(u1.y, n1, acc.y);
        acc.z = fmaf(u1.z, n1, acc.z); acc.w = fmaf(u1.w, n1, acc.w);
        acc.x = fmaf(u2.x, n2, acc.x); acc.y = fmaf(u2.y, n2, acc.y);
        acc.z = fmaf(u2.z, n2, acc.z); acc.w = fmaf(u2.w, n2, acc.w);
        acc.x = fmaf(u3.x, n3, acc.x); acc.y = fmaf(u3.y, n3, acc.y);
        acc.z = fmaf(u3.z, n3, acc.z); acc.w = fmaf(u3.w, n3, acc.w);
    }
    for (; e < c; e++) {
        int s0 = g_bsrc[base + e]; float n0 = g_bw[base + e];
        float4 u0 = ((const float4*)lin)[(size_t)s0 * 32 + lane];
        acc.x = fmaf(u0.x, n0, acc.x); acc.y = fmaf(u0.y, n0, acc.y);
        acc.z = fmaf(u0.z, n0, acc.z); acc.w = fmaf(u0.w, n0, acc.w);
    }
    ((float4*)out)[(size_t)d * 32 + lane] = acc;
}

// ---------------------------------------------------------------------------

static inline int cdiv(long long a, long long b) { return (int)((a + b - 1) / b); }

extern "C" void kernel_launch(void* const* d_in, const int* in_sizes, int n_in,
                              void* d_out, int out_size)
{
    const float* x   = (const float*)d_in[0];
    const void*  ei  = d_in[1];
    const float* ew  = (const float*)d_in[2];
    const float* W1  = (const float*)d_in[3];
    const float* b1  = (const float*)d_in[4];
    const float* W2  = (const float*)d_in[5];
    const float* b2  = (const float*)d_in[6];
    float* out = (float*)d_out;

    const int HID = in_sizes[4];                 // 128
    const int K1  = in_sizes[3] / HID;           // 256
    const int N   = in_sizes[0] / K1;            // 100000
    const int E   = in_sizes[2];                 // 1600000

    float* A; float* B;
    cudaGetSymbolAddress((void**)&A, g_A);
    cudaGetSymbolAddress((void**)&B, g_B);

    const int T = 256;

    cudaFuncSetAttribute(k_tgemm<false>,
                         cudaFuncAttributeMaxDynamicSharedMemorySize, DYNSMEM);
    cudaFuncSetAttribute(k_tgemm<true>,
                         cudaFuncAttributeMaxDynamicSharedMemorySize, DYNSMEM);

    // Fork-join (R7-proven resource pattern: 1 side stream, 2 events).
    cudaStream_t side;
    cudaStreamCreateWithFlags(&side, cudaStreamNonBlocking);
    cudaEvent_t evFork, evJoin;
    cudaEventCreateWithFlags(&evFork, cudaEventDisableTiming);
    cudaEventCreateWithFlags(&evJoin, cudaEventDisableTiming);

    cudaEventRecord(evFork, 0);
    cudaStreamWaitEvent(side, evFork, 0);

    // --- side stream: bucket-CSR build + norm fold (hidden under GEMM1) ---
    k_setup<<<cdiv(N, T), T, 0, side>>>((const unsigned*)ei, N);
    k_fill<<<cdiv(E, T), T, 0, side>>>(ei, ew, E);
    k_degrow<<<cdiv((long long)N * 32, T), T, 0, side>>>(N);
    k_scale<<<cdiv((long long)N * BUCKET, T), T, 0, side>>>(N);
    cudaEventRecord(evJoin, side);

    // --- main stream: layer-1 GEMM ---
    k_tgemm<false><<<cdiv(N, 128), T, DYNSMEM>>>(x, W1, A, N, K1);

    cudaStreamWaitEvent(0, evJoin, 0);
    k_gather<<<cdiv((long long)N * 32, T), T>>>(A, b1, B, N);

    k_tgemm<true><<<cdiv(N, 128), T, DYNSMEM>>>(B, W2, A, N, HID);
    k_gather<<<cdiv((long long)N * 32, T), T>>>(A, b2, out, N);
}